// round 3
// baseline (speedup 1.0000x reference)
#include <cuda_runtime.h>
#include <cstdint>

// Problem constants (RFInterDAS): rf[8,128,2048], d_tx[8,384,192], d_rx/apod[128,384,192]
#define N_ANG     8
#define N_ANG_CTA 4              // angles per CTA
#define AG        (N_ANG/N_ANG_CTA)   // 2 angle groups
#define N_EL      128
#define N_SAMP    2048
#define NPIX      (384*192)      // 73728
#define TPB       256
#define PPT       4              // pixels per thread
#define TILE      (TPB*PPT)      // 1024
#define NTILES    (NPIX/TILE)    // 72
#define EG        4              // element groups
#define EPG       (N_EL/EG)      // 32 elements per CTA

__global__ void zero_out_kernel(float* __restrict__ out, int n) {
    int i = blockIdx.x * blockDim.x + threadIdx.x;
    if (i < n) out[i] = 0.0f;
}

extern __shared__ float srf[];   // 4 rows x 2048 floats = 32 KB

__device__ __forceinline__ void cp_async16(uint32_t dst_smem, const void* src) {
    asm volatile("cp.async.cg.shared.global [%0], [%1], 16;\n"
                 :: "r"(dst_smem), "l"(src) : "memory");
}
__device__ __forceinline__ void cp_async_commit() {
    asm volatile("cp.async.commit_group;\n" ::: "memory");
}
__device__ __forceinline__ void cp_async_wait0() {
    asm volatile("cp.async.wait_group 0;\n" ::: "memory");
}

__global__ __launch_bounds__(TPB, 3)
void das_kernel(const float* __restrict__ rf,
                const float* __restrict__ t0,
                const float* __restrict__ d_tx,
                const float* __restrict__ d_rx,
                const float* __restrict__ fs_p,
                const float* __restrict__ c0_p,
                const float* __restrict__ apod,
                float* __restrict__ out)
{
    const int tile  = blockIdx.x;
    const int eg    = blockIdx.y;
    const int abase = blockIdx.z * N_ANG_CTA;
    const int tid   = threadIdx.x;

    const float fs    = *fs_p;
    const float c0    = *c0_p;
    const float scale = fs / c0;

    const uint32_t srf_s = (uint32_t)__cvta_generic_to_shared(srf);

    // Per-pixel, per-angle tx delay (in samples) held in registers.
    int   pix[PPT];
    float txs[PPT][N_ANG_CTA];
    float acc[PPT][N_ANG_CTA];
    float t0fs[N_ANG_CTA];
#pragma unroll
    for (int a = 0; a < N_ANG_CTA; a++) t0fs[a] = t0[abase + a] * fs;
#pragma unroll
    for (int k = 0; k < PPT; k++) {
        pix[k] = tile * TILE + k * TPB + tid;
#pragma unroll
        for (int a = 0; a < N_ANG_CTA; a++) {
            txs[k][a] = fmaf(d_tx[(abase + a) * NPIX + pix[k]], scale, t0fs[a]);
            acc[k][a] = 0.0f;
        }
    }

    const int e0 = eg * EPG;
    for (int e = e0; e < e0 + EPG; e++) {
        __syncthreads();  // previous iteration's reads done before overwrite
        // Stage rf rows for 4 angles, element e: 2048 x 16B via cp.async.
#pragma unroll
        for (int j = 0; j < (N_ANG_CTA * N_SAMP / 4) / TPB; j++) {  // 8 iters
            int q  = j * TPB + tid;          // float4 index in [0, 2048)
            int a  = q >> 9;                 // q / 512
            int c4 = q & 511;
            const float4* src =
                reinterpret_cast<const float4*>(
                    rf + ((size_t)((abase + a) * N_EL + e)) * N_SAMP) + c4;
            cp_async16(srf_s + (uint32_t)q * 16u, src);
        }
        cp_async_commit();

        // Overlap: pull the per-element streaming operands while copies fly.
        float rx[PPT], ap[PPT];
#pragma unroll
        for (int k = 0; k < PPT; k++) {
            rx[k] = d_rx[(size_t)e * NPIX + pix[k]] * scale;
            ap[k] = apod[(size_t)e * NPIX + pix[k]];
        }

        cp_async_wait0();
        __syncthreads();

#pragma unroll
        for (int k = 0; k < PPT; k++) {
#pragma unroll
            for (int a = 0; a < N_ANG_CTA; a++) {
                // All delay terms are >= 0, so s >= 0: only the upper clamp
                // (matching the reference's n_samples-1.001) is needed.
                float s = fminf(txs[k][a] + rx[k], 2046.999f);
                int   i = (int)s;            // s >= 0 -> trunc == floor
                float f = s - (float)i;
                const float* row = srf + a * N_SAMP + i;
                float lo = row[0];
                float hi = row[1];
                float sm = fmaf(f, hi - lo, lo);
                acc[k][a] = fmaf(sm, ap[k], acc[k][a]);
            }
        }
    }

    // Exactly EG(=4) commutative float adds per output element.
#pragma unroll
    for (int k = 0; k < PPT; k++)
#pragma unroll
        for (int a = 0; a < N_ANG_CTA; a++)
            atomicAdd(&out[(abase + a) * NPIX + pix[k]], acc[k][a]);
}

extern "C" void kernel_launch(void* const* d_in, const int* in_sizes, int n_in,
                              void* d_out, int out_size)
{
    const float* rf   = (const float*)d_in[0];
    const float* t0   = (const float*)d_in[1];
    const float* d_tx = (const float*)d_in[2];
    const float* d_rx = (const float*)d_in[3];
    const float* fs   = (const float*)d_in[4];
    const float* c0   = (const float*)d_in[5];
    const float* apod = (const float*)d_in[6];
    float* out = (float*)d_out;

    cudaFuncSetAttribute(das_kernel,
                         cudaFuncAttributeMaxDynamicSharedMemorySize,
                         N_ANG_CTA * N_SAMP * (int)sizeof(float));

    zero_out_kernel<<<(out_size + TPB - 1) / TPB, TPB>>>(out, out_size);

    dim3 grid(NTILES, EG, AG);
    das_kernel<<<grid, TPB, N_ANG_CTA * N_SAMP * sizeof(float)>>>(
        rf, t0, d_tx, d_rx, fs, c0, apod, out);
}

// round 4
// speedup vs baseline: 1.0650x; 1.0650x over previous
#include <cuda_runtime.h>
#include <cstdint>

// rf[8,128,2048], t0[8], d_tx[8,384,192], d_rx/apod[128,384,192] -> out[8,384,192]
#define N_ANG     8
#define N_EL      128
#define N_SAMP    2048
#define N_STAGE   1152           // max sample index used is < 1059 (physics bound)
#define NPIX      (384*192)      // 73728
#define TPB       256
#define PPT       2
#define TILE      (TPB*PPT)      // 512
#define NTILES    (NPIX/TILE)    // 144
#define EG        8              // element groups
#define EPG       (N_EL/EG)      // 16 elements per CTA
#define BUF_FLOATS (N_ANG*N_STAGE)       // 9216 floats per buffer
#define BUF_BYTES  (BUF_FLOATS*4)        // 36864 B
#define F4_PER_ROW (N_STAGE/4)           // 288
#define F4_PER_BUF (N_ANG*F4_PER_ROW)    // 2304
#define STAGE_ITERS (F4_PER_BUF/TPB)     // 9

__global__ void zero_out_kernel(float* __restrict__ out, int n) {
    int i = blockIdx.x * blockDim.x + threadIdx.x;
    if (i < n) out[i] = 0.0f;
}

extern __shared__ float srf[];   // 2 x 36864 B = 73728 B

__device__ __forceinline__ void cp_async16(uint32_t dst_smem, const void* src) {
    asm volatile("cp.async.cg.shared.global [%0], [%1], 16;\n"
                 :: "r"(dst_smem), "l"(src) : "memory");
}
__device__ __forceinline__ void cp_async_commit() {
    asm volatile("cp.async.commit_group;\n" ::: "memory");
}
__device__ __forceinline__ void cp_async_wait1() {
    asm volatile("cp.async.wait_group 1;\n" ::: "memory");
}
__device__ __forceinline__ void cp_async_wait0() {
    asm volatile("cp.async.wait_group 0;\n" ::: "memory");
}

__device__ __forceinline__ void stage_element(const float* __restrict__ rf,
                                              uint32_t srf_s, int e, int buf, int tid)
{
#pragma unroll
    for (int j = 0; j < STAGE_ITERS; j++) {
        int q  = j * TPB + tid;          // float4 index in [0, 2304)
        int a  = q / F4_PER_ROW;
        int c4 = q - a * F4_PER_ROW;
        const float4* src =
            reinterpret_cast<const float4*>(
                rf + ((size_t)(a * N_EL + e)) * N_SAMP) + c4;
        uint32_t dst = srf_s + (uint32_t)buf * BUF_BYTES
                             + (uint32_t)a * (N_STAGE * 4)
                             + (uint32_t)c4 * 16u;
        cp_async16(dst, src);
    }
    cp_async_commit();
}

__global__ __launch_bounds__(TPB, 3)
void das_kernel(const float* __restrict__ rf,
                const float* __restrict__ t0,
                const float* __restrict__ d_tx,
                const float* __restrict__ d_rx,
                const float* __restrict__ fs_p,
                const float* __restrict__ c0_p,
                const float* __restrict__ apod,
                float* __restrict__ out)
{
    const int tile = blockIdx.x;
    const int eg   = blockIdx.y;
    const int tid  = threadIdx.x;

    const float fs    = *fs_p;
    const float c0    = *c0_p;
    const float scale = fs / c0;

    const uint32_t srf_s = (uint32_t)__cvta_generic_to_shared(srf);

    int   pix[PPT];
    float txs[PPT][N_ANG];
    float acc[PPT][N_ANG];
#pragma unroll
    for (int k = 0; k < PPT; k++) {
        pix[k] = tile * TILE + k * TPB + tid;
#pragma unroll
        for (int a = 0; a < N_ANG; a++) {
            txs[k][a] = fmaf(d_tx[a * NPIX + pix[k]], scale, t0[a] * fs);
            acc[k][a] = 0.0f;
        }
    }

    const int e0 = eg * EPG;

    // Prologue: stage first element, prefetch its rx/apod.
    stage_element(rf, srf_s, e0, 0, tid);
    float rxn[PPT], apn[PPT];
#pragma unroll
    for (int k = 0; k < PPT; k++) {
        rxn[k] = d_rx[(size_t)e0 * NPIX + pix[k]] * scale;
        apn[k] = apod[(size_t)e0 * NPIX + pix[k]];
    }

    for (int ei = 0; ei < EPG; ei++) {
        const int e   = e0 + ei;
        const int buf = ei & 1;

        float rxc[PPT], apc[PPT];
#pragma unroll
        for (int k = 0; k < PPT; k++) { rxc[k] = rxn[k]; apc[k] = apn[k]; }

        if (ei + 1 < EPG) {
            // Stage next element into the other buffer (safe: that buffer's
            // previous gather finished at the barrier ending iteration ei-1).
            stage_element(rf, srf_s, e + 1, buf ^ 1, tid);
            // Prefetch next element's streaming operands (latency hidden by gather).
#pragma unroll
            for (int k = 0; k < PPT; k++) {
                rxn[k] = d_rx[(size_t)(e + 1) * NPIX + pix[k]] * scale;
                apn[k] = apod[(size_t)(e + 1) * NPIX + pix[k]];
            }
            cp_async_wait1();   // current element's group complete
        } else {
            cp_async_wait0();
        }
        __syncthreads();        // staged data visible to all warps

        const float* bufp = srf + buf * BUF_FLOATS;
#pragma unroll
        for (int k = 0; k < PPT; k++) {
#pragma unroll
            for (int a = 0; a < N_ANG; a++) {
                float s = fminf(txs[k][a] + rxc[k], 2046.999f); // s >= 0 always
                int   i = (int)s;                // trunc == floor for s >= 0
                float f = s - (float)i;
                const float* row = bufp + a * N_STAGE + i;
                float lo = row[0];
                float hi = row[1];
                float sm = fmaf(f, hi - lo, lo);
                acc[k][a] = fmaf(sm, apc[k], acc[k][a]);
            }
        }
        __syncthreads();        // gathers done before this buffer is restaged
    }

    // Exactly EG commutative float adds per output element: deterministic.
#pragma unroll
    for (int k = 0; k < PPT; k++)
#pragma unroll
        for (int a = 0; a < N_ANG; a++)
            atomicAdd(&out[a * NPIX + pix[k]], acc[k][a]);
}

extern "C" void kernel_launch(void* const* d_in, const int* in_sizes, int n_in,
                              void* d_out, int out_size)
{
    const float* rf   = (const float*)d_in[0];
    const float* t0   = (const float*)d_in[1];
    const float* d_tx = (const float*)d_in[2];
    const float* d_rx = (const float*)d_in[3];
    const float* fs   = (const float*)d_in[4];
    const float* c0   = (const float*)d_in[5];
    const float* apod = (const float*)d_in[6];
    float* out = (float*)d_out;

    cudaFuncSetAttribute(das_kernel,
                         cudaFuncAttributeMaxDynamicSharedMemorySize,
                         2 * BUF_BYTES);

    zero_out_kernel<<<(out_size + TPB - 1) / TPB, TPB>>>(out, out_size);

    dim3 grid(NTILES, EG);
    das_kernel<<<grid, TPB, 2 * BUF_BYTES>>>(
        rf, t0, d_tx, d_rx, fs, c0, apod, out);
}

// round 5
// speedup vs baseline: 1.1520x; 1.0817x over previous
#include <cuda_runtime.h>
#include <cstdint>

// rf[8,128,2048], t0[8], d_tx[8,384,192], d_rx/apod[128,384,192] -> out[8,384,192]
#define N_ANG     8
#define N_EL      128
#define N_SAMP    2048
#define N_STAGE   1152           // max sample index < 1059 (t0max*fs + 2*DEPTH/c0*fs)
#define NPIX      (384*192)      // 73728
#define TPB       256
#define PPT       4
#define TILE      (TPB*PPT)      // 1024
#define NTILES    (NPIX/TILE)    // 72
#define EG        8              // element groups
#define EPG       (N_EL/EG)      // 16 elements per CTA
#define BUF_FLOATS (N_ANG*N_STAGE)       // 9216 floats per buffer
#define BUF_BYTES  (BUF_FLOATS*4)        // 36864 B
#define F4_PER_ROW (N_STAGE/4)           // 288
#define F4_PER_BUF (N_ANG*F4_PER_ROW)    // 2304
#define STAGE_ITERS (F4_PER_BUF/TPB)     // 9

__global__ void zero_out_kernel(float* __restrict__ out, int n) {
    int i = blockIdx.x * blockDim.x + threadIdx.x;
    if (i < n) out[i] = 0.0f;
}

extern __shared__ float srf[];   // 2 x 36864 B = 73728 B

__device__ __forceinline__ void cp_async16(uint32_t dst_smem, const void* src) {
    asm volatile("cp.async.cg.shared.global [%0], [%1], 16;\n"
                 :: "r"(dst_smem), "l"(src) : "memory");
}
__device__ __forceinline__ void cp_async_commit() {
    asm volatile("cp.async.commit_group;\n" ::: "memory");
}
__device__ __forceinline__ void cp_async_wait1() {
    asm volatile("cp.async.wait_group 1;\n" ::: "memory");
}
__device__ __forceinline__ void cp_async_wait0() {
    asm volatile("cp.async.wait_group 0;\n" ::: "memory");
}

__device__ __forceinline__ void stage_element(const float* __restrict__ rf,
                                              uint32_t srf_s, int e, int buf, int tid)
{
#pragma unroll
    for (int j = 0; j < STAGE_ITERS; j++) {
        int q  = j * TPB + tid;          // float4 index in [0, 2304)
        int a  = q / F4_PER_ROW;
        int c4 = q - a * F4_PER_ROW;
        const float4* src =
            reinterpret_cast<const float4*>(
                rf + ((size_t)(a * N_EL + e)) * N_SAMP) + c4;
        uint32_t dst = srf_s + (uint32_t)buf * BUF_BYTES
                             + (uint32_t)a * (N_STAGE * 4)
                             + (uint32_t)c4 * 16u;
        cp_async16(dst, src);
    }
    cp_async_commit();
}

__global__ __launch_bounds__(TPB, 2)
void das_kernel(const float* __restrict__ rf,
                const float* __restrict__ t0,
                const float* __restrict__ d_tx,
                const float* __restrict__ d_rx,
                const float* __restrict__ fs_p,
                const float* __restrict__ c0_p,
                const float* __restrict__ apod,
                float* __restrict__ out)
{
    const int tile = blockIdx.x;
    const int eg   = blockIdx.y;
    const int tid  = threadIdx.x;

    const float fs    = *fs_p;
    const float c0    = *c0_p;
    const float scale = fs / c0;

    const uint32_t srf_s = (uint32_t)__cvta_generic_to_shared(srf);

    int   pix[PPT];
    float txs[PPT][N_ANG];
    float acc[PPT][N_ANG];
#pragma unroll
    for (int k = 0; k < PPT; k++) {
        pix[k] = tile * TILE + k * TPB + tid;
#pragma unroll
        for (int a = 0; a < N_ANG; a++) {
            txs[k][a] = fmaf(d_tx[a * NPIX + pix[k]], scale, t0[a] * fs);
            acc[k][a] = 0.0f;
        }
    }

    const int e0 = eg * EPG;

    // Prologue: stage first element, prefetch its rx/apod.
    stage_element(rf, srf_s, e0, 0, tid);
    float rxn[PPT], apn[PPT];
#pragma unroll
    for (int k = 0; k < PPT; k++) {
        rxn[k] = d_rx[(size_t)e0 * NPIX + pix[k]] * scale;
        apn[k] = apod[(size_t)e0 * NPIX + pix[k]];
    }

    for (int ei = 0; ei < EPG; ei++) {
        const int e   = e0 + ei;
        const int buf = ei & 1;

        float rxc[PPT], apc[PPT];
#pragma unroll
        for (int k = 0; k < PPT; k++) { rxc[k] = rxn[k]; apc[k] = apn[k]; }

        if (ei + 1 < EPG) {
            // Stage next element into the other buffer (its previous gather
            // finished at the barrier that ended iteration ei-1).
            stage_element(rf, srf_s, e + 1, buf ^ 1, tid);
            // Prefetch next element's streaming operands under the gather.
#pragma unroll
            for (int k = 0; k < PPT; k++) {
                rxn[k] = d_rx[(size_t)(e + 1) * NPIX + pix[k]] * scale;
                apn[k] = apod[(size_t)(e + 1) * NPIX + pix[k]];
            }
            cp_async_wait1();   // current element's group complete
        } else {
            cp_async_wait0();
        }
        __syncthreads();        // staged data visible to all warps

        const float* bufp = srf + buf * BUF_FLOATS;
#pragma unroll
        for (int k = 0; k < PPT; k++) {
#pragma unroll
            for (int a = 0; a < N_ANG; a++) {
                float s = fminf(txs[k][a] + rxc[k], 2046.999f); // s >= 0 always
                int   i = (int)s;                // trunc == floor for s >= 0
                float f = s - (float)i;
                const float* row = bufp + a * N_STAGE + i;
                float lo = row[0];
                float hi = row[1];
                float sm = fmaf(f, hi - lo, lo);
                acc[k][a] = fmaf(sm, apc[k], acc[k][a]);
            }
        }
        __syncthreads();        // gathers done before this buffer is restaged
    }

    // Exactly EG commutative float adds per output element: deterministic.
#pragma unroll
    for (int k = 0; k < PPT; k++)
#pragma unroll
        for (int a = 0; a < N_ANG; a++)
            atomicAdd(&out[a * NPIX + pix[k]], acc[k][a]);
}

extern "C" void kernel_launch(void* const* d_in, const int* in_sizes, int n_in,
                              void* d_out, int out_size)
{
    const float* rf   = (const float*)d_in[0];
    const float* t0   = (const float*)d_in[1];
    const float* d_tx = (const float*)d_in[2];
    const float* d_rx = (const float*)d_in[3];
    const float* fs   = (const float*)d_in[4];
    const float* c0   = (const float*)d_in[5];
    const float* apod = (const float*)d_in[6];
    float* out = (float*)d_out;

    cudaFuncSetAttribute(das_kernel,
                         cudaFuncAttributeMaxDynamicSharedMemorySize,
                         2 * BUF_BYTES);

    zero_out_kernel<<<(out_size + TPB - 1) / TPB, TPB>>>(out, out_size);

    dim3 grid(NTILES, EG);
    das_kernel<<<grid, TPB, 2 * BUF_BYTES>>>(
        rf, t0, d_tx, d_rx, fs, c0, apod, out);
}